// round 15
// baseline (speedup 1.0000x reference)
#include <cuda_runtime.h>
#include <cuda_bf16.h>
#include <math.h>
#include <stdint.h>

// Problem constants
#define BB 2
#define SS 2048
#define DD 1024
#define HH 16
#define HDD 64
#define MM (BB*SS)            // 4096
#define LN_EPS 1e-5f
#define EXP_C 0.04508422f     // (1/32) * log2(e)

typedef __nv_bfloat16 bf16;
typedef __nv_bfloat162 bf162;

// Scratch (device globals: allocation-free)
__device__ bf16 g_xb[MM*DD];
__device__ bf16 g_wqkv[3*DD*DD];    // rows 0-1023: wq, 1024-2047: wk, 2048-3071: wv
__device__ bf16 g_wob[DD*DD];
__device__ float g_bqkv[3*DD];
__device__ bf16 g_Qb[MM*DD], g_Kb[MM*DD], g_Vb[MM*DD];
__device__ bf16 g_Cb[MM*DD];
__device__ float g_R[MM*DD];

// ---------------------------------------------------------------------------
// mma m16n8k16 bf16 (f32 accum) + ldmatrix helpers
// ---------------------------------------------------------------------------
#define MMA_BF16(d, a, b)                                                     \
    asm volatile(                                                             \
        "mma.sync.aligned.m16n8k16.row.col.f32.bf16.bf16.f32 "                \
        "{%0,%1,%2,%3}, {%4,%5,%6,%7}, {%8,%9}, {%0,%1,%2,%3};"               \
        : "+f"((d)[0]), "+f"((d)[1]), "+f"((d)[2]), "+f"((d)[3])              \
        : "r"((a)[0]), "r"((a)[1]), "r"((a)[2]), "r"((a)[3]),                 \
          "r"((b)[0]), "r"((b)[1]))

#define LDSM_X4(r0, r1, r2, r3, saddr)                                        \
    asm volatile(                                                             \
        "ldmatrix.sync.aligned.m8n8.x4.shared.b16 {%0,%1,%2,%3}, [%4];"       \
        : "=r"(r0), "=r"(r1), "=r"(r2), "=r"(r3) : "r"(saddr))

#define LDSM_X4T(r0, r1, r2, r3, saddr)                                       \
    asm volatile(                                                             \
        "ldmatrix.sync.aligned.m8n8.x4.trans.shared.b16 {%0,%1,%2,%3}, [%4];" \
        : "=r"(r0), "=r"(r1), "=r"(r2), "=r"(r3) : "r"(saddr))

__device__ __forceinline__ void cp16(uint32_t saddr, const void* gptr) {
    asm volatile("cp.async.cg.shared.global [%0], [%1], 16;" :: "r"(saddr), "l"(gptr));
}
__device__ __forceinline__ float ex2(float x) {
    float y;
    asm("ex2.approx.f32 %0, %1;" : "=f"(y) : "f"(x));
    return y;
}
__device__ __forceinline__ uint32_t pack_bf162(float a, float b) {
    uint32_t r;
    asm("cvt.rn.bf16x2.f32 %0, %1, %2;" : "=r"(r) : "f"(b), "f"(a));
    return r;
}
__device__ __forceinline__ uint32_t ld_u32(const bf16* p) {
    return *(const uint32_t*)p;
}

// ---------------------------------------------------------------------------
// Fused fp32 -> bf16 convert for x + 4 weights + bias pack (single launch)
// ---------------------------------------------------------------------------
__global__ __launch_bounds__(256) void cvt_all(
    const float* __restrict__ x,  const float* __restrict__ wq,
    const float* __restrict__ wk, const float* __restrict__ wv,
    const float* __restrict__ wo,
    const float* __restrict__ bq, const float* __restrict__ bk,
    const float* __restrict__ bv,
    bf16* __restrict__ xb, bf16* __restrict__ wqkv, bf16* __restrict__ wob,
    float* __restrict__ bqkv)
{
    const int NX = MM*DD/4;      // float4 count for x
    const int NW = DD*DD/4;      // float4 count per weight
    const int NB = DD/4;         // float4 count per bias
    const int total  = NX + 4*NW;
    const int total2 = total + 3*NB;
    int stride = gridDim.x * blockDim.x;
    for (int i = blockIdx.x * blockDim.x + threadIdx.x; i < total2; i += stride) {
        if (i < total) {
            const float* s; bf16* d; int j;
            if (i < NX) { s = x; d = xb; j = i; }
            else {
                int k = i - NX;
                int w = k / NW;
                j = k - w * NW;
                s = (w == 0) ? wq : (w == 1) ? wk : (w == 2) ? wv : wo;
                d = (w == 3) ? wob : wqkv + (size_t)w * DD * DD;
            }
            float4 v = ((const float4*)s)[j];
            bf162* dp = (bf162*)d;
            dp[2*j]   = __floats2bfloat162_rn(v.x, v.y);
            dp[2*j+1] = __floats2bfloat162_rn(v.z, v.w);
        } else {
            int k = i - total;
            int w = k / NB;
            int j = k - w * NB;
            const float* s = (w == 0) ? bq : (w == 1) ? bk : bv;
            ((float4*)bqkv)[w*NB + j] = ((const float4*)s)[j];
        }
    }
}

// ---------------------------------------------------------------------------
// GEMM (NT) bf16: C[M,N] = A[M,K] * B[N,K]^T + bias[N]
// 128x128 tile, BK=32, 256 threads (8 warps 2x4, warp tile 64x32),
// 3-stage cp.async pipeline, ONE __syncthreads per chunk.
// ---------------------------------------------------------------------------
#define GST 40
#define GSTG (256*GST)                 // elems per stage (A 128*GST + B 128*GST)
#define GEMM_SMEM (3*GSTG*2)           // 61440 B

template<int ROUTE>
__global__ __launch_bounds__(256, 2) void gemm_bf16(
    const bf16* __restrict__ A, const bf16* __restrict__ B,
    const float* __restrict__ bias,
    bf16* __restrict__ O0, bf16* __restrict__ O1, bf16* __restrict__ O2,
    float* __restrict__ Ofp,
    int M, int N, int K)
{
    extern __shared__ bf16 smem[];
    const uint32_t sm_u32 = (uint32_t)__cvta_generic_to_shared(smem);

    const int bm = blockIdx.y * 128;
    const int bn = blockIdx.x * 128;
    const int tid = threadIdx.x;
    const int warp = tid >> 5, lane = tid & 31;
    const int g = lane >> 2, t4 = lane & 3;
    const int wm = (warp & 1) * 64;
    const int wn = (warp >> 1) * 32;

    const int lrow = tid >> 1;
    const int lch  = tid & 1;

    float acc[4][4][4];
    #pragma unroll
    for (int i = 0; i < 4; i++)
        #pragma unroll
        for (int j = 0; j < 4; j++)
            #pragma unroll
            for (int r = 0; r < 4; r++) acc[i][j][r] = 0.f;

    const bf16* gA = A + (size_t)(bm + lrow) * K;
    const bf16* gB = B + (size_t)(bn + lrow) * K;

    auto load_tile = [&](int ck, int st) {
        int kt = ck * 32;
        uint32_t sbase = sm_u32 + 2u * (st * GSTG + lrow * GST);
        #pragma unroll
        for (int cc = 0; cc < 2; cc++) {
            int c = lch + 2*cc;   // 0..3 (8-elem chunks)
            cp16(sbase + 16u*c, gA + kt + c*8);
            cp16(sbase + 2u*(128*GST) + 16u*c, gB + kt + c*8);
        }
        asm volatile("cp.async.commit_group;" ::: "memory");
    };

    const int NC = K / 32;
    load_tile(0, 0);
    load_tile(1, 1);

    for (int ck = 0; ck < NC; ck++) {
        if (ck == NC - 1) {
            asm volatile("cp.async.wait_group 0;" ::: "memory");
        } else {
            asm volatile("cp.async.wait_group 1;" ::: "memory");
        }
        __syncthreads();
        if (ck + 2 < NC) load_tile(ck + 2, (ck + 2) % 3);

        const bf16* sA = smem + (ck % 3) * GSTG;
        const bf16* sB = sA + 128*GST;

        #pragma unroll
        for (int ks = 0; ks < 2; ks++) {
            const int c = ks*16 + 2*t4;
            uint32_t ah[4][4];
            #pragma unroll
            for (int mt = 0; mt < 4; mt++) {
                int r0 = (wm + mt*16 + g) * GST + c;
                ah[mt][0] = ld_u32(sA + r0);
                ah[mt][1] = ld_u32(sA + r0 + 8*GST);
                ah[mt][2] = ld_u32(sA + r0 + 8);
                ah[mt][3] = ld_u32(sA + r0 + 8*GST + 8);
            }
            #pragma unroll
            for (int nt = 0; nt < 4; nt++) {
                int n0 = (wn + nt*8 + g) * GST + c;
                uint32_t bh[2];
                bh[0] = ld_u32(sB + n0);
                bh[1] = ld_u32(sB + n0 + 8);
                #pragma unroll
                for (int mt = 0; mt < 4; mt++)
                    MMA_BF16(acc[mt][nt], ah[mt], bh);
            }
        }
    }

    // epilogue
    bf16* Obf = O0;
    int coff = bn;
    float osc = 1.0f;
    if (ROUTE) {
        int sect = bn >> 10;            // 0,1,2 (128-col blocks never straddle)
        Obf = (sect == 0) ? O0 : (sect == 1 ? O1 : O2);
        coff = bn & 1023;
        if (sect == 0) osc = EXP_C;     // pre-scale Q for fixed-base softmax
    }
    #pragma unroll
    for (int mt = 0; mt < 4; mt++) {
        #pragma unroll
        for (int nt = 0; nt < 4; nt++) {
            int row0 = bm + wm + mt*16 + g;
            int colg = bn + wn + nt*8 + 2*t4;       // for bias
            int col0 = coff + wn + nt*8 + 2*t4;     // for store
            float b0 = bias[colg], b1 = bias[colg + 1];
            float v00 = acc[mt][nt][0] + b0, v01 = acc[mt][nt][1] + b1;
            float v10 = acc[mt][nt][2] + b0, v11 = acc[mt][nt][3] + b1;
            if (ROUTE) {
                v00 *= osc; v01 *= osc; v10 *= osc; v11 *= osc;
                *(uint32_t*)(Obf + (size_t)row0 * DD + col0)       = pack_bf162(v00, v01);
                *(uint32_t*)(Obf + (size_t)(row0 + 8) * DD + col0) = pack_bf162(v10, v11);
            } else {
                *(float2*)(Ofp + (size_t)row0 * N + col0)       = make_float2(v00, v01);
                *(float2*)(Ofp + (size_t)(row0 + 8) * N + col0) = make_float2(v10, v11);
            }
        }
    }
}

// ---------------------------------------------------------------------------
// Flash attention bf16 (v4):
//  - fixed-base softmax (Q pre-scaled by EXP_C in the QKV GEMM epilogue)
//  - P in registers; Q frags hoisted; ONE __syncthreads per kv tile
//  - K AND V double-buffered via cp.async (one group per tile)
//  - K frags via ldmatrix.x4; V^T frags via ldmatrix.x4.trans (no transpose stores)
// smem layout (bf16 units): K0 [0,64*AST) K1 [64*AST,128*AST)
//                           V0 [128*AST,192*AST) V1 [192*AST,256*AST)
// Qs [0,128*AST) aliases K0/K1 (dead after fragment extraction).
// ---------------------------------------------------------------------------
#define AST 72
#define ATT_SMEM (256*AST*2)   // 36864 B

__global__ __launch_bounds__(256, 2) void attn_bf16(
    const bf16* __restrict__ Q, const bf16* __restrict__ K,
    const bf16* __restrict__ V, bf16* __restrict__ O)
{
    extern __shared__ bf16 sm[];
    bf16* Qs = sm;
    const uint32_t sm_u32 = (uint32_t)__cvta_generic_to_shared(sm);

    const int q0 = blockIdx.x * 128;
    const int h  = blockIdx.y;
    const int b  = blockIdx.z;
    const int tid = threadIdx.x;
    const int warp = tid >> 5, lane = tid & 31;
    const int g = lane >> 2, t4 = lane & 3;
    const int w16 = warp * 16;

    const int l8   = lane & 7;
    const int selK = (lane >> 3) & 1;
    const int selN = (lane >> 4) & 1;
    // K (non-trans): matrices (n-blk even klo, even khi, odd klo, odd khi)
    const uint32_t km_inv = (uint32_t)(((selN*8 + l8) * AST + selK*8) * 2);
    // V (trans): matrices (klo hd-even, khi hd-even, klo hd-odd, khi hd-odd)
    const uint32_t vm_inv = (uint32_t)(((selK*8 + l8) * AST + selN*8) * 2);

    const size_t base = (size_t)b * SS * DD + (size_t)h * HDD;

    // ---- load Q tile (128 x 64) into Qs (aliases K bufs) ----
    {
        int r = tid >> 1;
        int c0 = (tid & 1) * 32;
        const bf16* src = Q + base + (size_t)(q0 + r) * DD + c0;
        bf16* dst = Qs + r*AST + c0;
        #pragma unroll
        for (int i = 0; i < 4; i++)
            *(uint4*)(dst + i*8) = *(const uint4*)(src + i*8);
    }
    __syncthreads();   // Qs ready

    // ---- hoist Q fragments ----
    uint32_t qa[4][4];
    #pragma unroll
    for (int ks = 0; ks < 4; ks++) {
        const int c = ks*16 + 2*t4;
        int r0 = (w16 + g) * AST + c;
        qa[ks][0] = ld_u32(Qs + r0);
        qa[ks][1] = ld_u32(Qs + r0 + 8*AST);
        qa[ks][2] = ld_u32(Qs + r0 + 8);
        qa[ks][3] = ld_u32(Qs + r0 + 8*AST + 8);
    }
    __syncthreads();   // all warps extracted; Qs region reusable

    // ---- per-tile load assignment (K and V identical pattern) ----
    const int kr  = tid >> 2;            // 0..63
    const int kc0 = (tid & 3) * 16;      // 0,16,32,48
    auto issue_tile = [&](int it, int bsel) {
        uint32_t kb = sm_u32 + 2u*(bsel*64*AST)       + 2u*(kr*AST + kc0);
        uint32_t vb = sm_u32 + 2u*((2 + bsel)*64*AST) + 2u*(kr*AST + kc0);
        const bf16* kg = K + base + (size_t)(it*64 + kr) * DD + kc0;
        const bf16* vg = V + base + (size_t)(it*64 + kr) * DD + kc0;
        cp16(kb,       kg);
        cp16(kb + 16u, kg + 8);
        cp16(vb,       vg);
        cp16(vb + 16u, vg + 8);
        asm volatile("cp.async.commit_group;" ::: "memory");
    };
    issue_tile(0, 0);

    float o[8][4];
    #pragma unroll
    for (int nf = 0; nf < 8; nf++)
        #pragma unroll
        for (int r = 0; r < 4; r++) o[nf][r] = 0.f;
    float lsum[2] = {0.f, 0.f};

    int buf = 0;
    for (int it = 0; it < SS/64; it++) {
        asm volatile("cp.async.wait_group 0;" ::: "memory");
        __syncthreads();   // tile it visible; all warps done with tile it-1 bufs
        if (it + 1 < SS/64) issue_tile(it + 1, buf ^ 1);

        const uint32_t kbase = sm_u32 + 2u*(buf*64*AST);
        const uint32_t vbase = sm_u32 + 2u*((2 + buf)*64*AST);

        // S = Q K^T
        float s[8][4];
        #pragma unroll
        for (int nf = 0; nf < 8; nf++)
            #pragma unroll
            for (int r = 0; r < 4; r++) s[nf][r] = 0.f;

        #pragma unroll
        for (int ks = 0; ks < 4; ks++) {
            #pragma unroll
            for (int i = 0; i < 4; i++) {
                uint32_t b0, b1, b2, b3;
                uint32_t addr = kbase + km_inv + (uint32_t)(i*16*AST*2 + ks*32);
                LDSM_X4(b0, b1, b2, b3, addr);
                uint32_t be[2]  = {b0, b1};
                uint32_t bo_[2] = {b2, b3};
                MMA_BF16(s[2*i],     qa[ks], be);
                MMA_BF16(s[2*i + 1], qa[ks], bo_);
            }
        }

        // p = exp2(s) (Q pre-scaled); accumulate row sums
        #pragma unroll
        for (int nf = 0; nf < 8; nf++) {
            s[nf][0] = ex2(s[nf][0]);
            s[nf][1] = ex2(s[nf][1]);
            s[nf][2] = ex2(s[nf][2]);
            s[nf][3] = ex2(s[nf][3]);
            lsum[0] += s[nf][0] + s[nf][1];
            lsum[1] += s[nf][2] + s[nf][3];
        }

        // O += P @ V   (V^T frags via ldmatrix.x4.trans on row-major V tile)
        #pragma unroll
        for (int ks = 0; ks < 4; ks++) {
            uint32_t pa[4];
            pa[0] = pack_bf162(s[2*ks][0],   s[2*ks][1]);
            pa[1] = pack_bf162(s[2*ks][2],   s[2*ks][3]);
            pa[2] = pack_bf162(s[2*ks+1][0], s[2*ks+1][1]);
            pa[3] = pack_bf162(s[2*ks+1][2], s[2*ks+1][3]);
            #pragma unroll
            for (int i = 0; i < 4; i++) {
                uint32_t b0, b1, b2, b3;
                uint32_t addr = vbase + vm_inv + (uint32_t)(ks*16*AST*2 + i*32);
                LDSM_X4T(b0, b1, b2, b3, addr);
                uint32_t be[2]  = {b0, b1};
                uint32_t bo_[2] = {b2, b3};
                MMA_BF16(o[2*i],     pa, be);
                MMA_BF16(o[2*i + 1], pa, bo_);
            }
        }
        buf ^= 1;
    }

    lsum[0] += __shfl_xor_sync(0xffffffffu, lsum[0], 1);
    lsum[0] += __shfl_xor_sync(0xffffffffu, lsum[0], 2);
    lsum[1] += __shfl_xor_sync(0xffffffffu, lsum[1], 1);
    lsum[1] += __shfl_xor_sync(0xffffffffu, lsum[1], 2);

    float inv0 = 1.f / lsum[0];
    float inv1 = 1.f / lsum[1];
    #pragma unroll
    for (int nf = 0; nf < 8; nf++) {
        int row0 = q0 + w16 + g;
        int col  = nf*8 + 2*t4;
        size_t o0 = base + (size_t)row0 * DD + col;
        size_t o1 = base + (size_t)(row0 + 8) * DD + col;
        *(uint32_t*)(O + o0) = pack_bf162(o[nf][0]*inv0, o[nf][1]*inv0);
        *(uint32_t*)(O + o1) = pack_bf162(o[nf][2]*inv1, o[nf][3]*inv1);
    }
}

// ---------------------------------------------------------------------------
// Fused residual-add + LayerNorm
// ---------------------------------------------------------------------------
__global__ __launch_bounds__(256) void add_ln_kernel(
    const float* __restrict__ x, const float* __restrict__ res,
    const float* __restrict__ gamma, const float* __restrict__ beta,
    float* __restrict__ out)
{
    const int row = blockIdx.x;
    const int t = threadIdx.x;
    const size_t off = (size_t)row * DD + t*4;

    float4 xv = *(const float4*)(x + off);
    float4 rv = *(const float4*)(res + off);
    float4 y;
    y.x = xv.x + rv.x; y.y = xv.y + rv.y; y.z = xv.z + rv.z; y.w = xv.w + rv.w;

    float sum = y.x + y.y + y.z + y.w;
    float sq  = y.x*y.x + y.y*y.y + y.z*y.z + y.w*y.w;

    #pragma unroll
    for (int msk = 16; msk >= 1; msk >>= 1) {
        sum += __shfl_xor_sync(0xffffffffu, sum, msk);
        sq  += __shfl_xor_sync(0xffffffffu, sq,  msk);
    }
    __shared__ float ssum[8], ssq[8], s_mu, s_rstd;
    int wid = t >> 5, lane = t & 31;
    if (lane == 0) { ssum[wid] = sum; ssq[wid] = sq; }
    __syncthreads();
    if (t == 0) {
        float ts = 0.f, tq = 0.f;
        #pragma unroll
        for (int i = 0; i < 8; i++) { ts += ssum[i]; tq += ssq[i]; }
        float mu = ts * (1.0f / DD);
        float var = tq * (1.0f / DD) - mu * mu;
        s_mu = mu;
        s_rstd = rsqrtf(var + LN_EPS);
    }
    __syncthreads();
    float mu = s_mu, rstd = s_rstd;

    float4 gv = *(const float4*)(gamma + t*4);
    float4 bv = *(const float4*)(beta + t*4);
    float4 oo;
    oo.x = (y.x - mu) * rstd * gv.x + bv.x;
    oo.y = (y.y - mu) * rstd * gv.y + bv.y;
    oo.z = (y.z - mu) * rstd * gv.z + bv.z;
    oo.w = (y.w - mu) * rstd * gv.w + bv.w;
    *(float4*)(out + off) = oo;
}

// ---------------------------------------------------------------------------
extern "C" void kernel_launch(void* const* d_in, const int* in_sizes, int n_in,
                              void* d_out, int out_size)
{
    const float* x     = (const float*)d_in[0];
    const float* wq    = (const float*)d_in[1];
    const float* bq    = (const float*)d_in[2];
    const float* wk    = (const float*)d_in[3];
    const float* bk    = (const float*)d_in[4];
    const float* wv    = (const float*)d_in[5];
    const float* bv    = (const float*)d_in[6];
    const float* wo    = (const float*)d_in[7];
    const float* bo    = (const float*)d_in[8];
    const float* gamma = (const float*)d_in[9];
    const float* beta  = (const float*)d_in[10];
    float* out = (float*)d_out;

    bf16 *xb, *wqkv, *wob, *Qb, *Kb, *Vb, *Cb;
    float *bqkv, *Rp;
    cudaGetSymbolAddress((void**)&xb, g_xb);
    cudaGetSymbolAddress((void**)&wqkv, g_wqkv);
    cudaGetSymbolAddress((void**)&wob, g_wob);
    cudaGetSymbolAddress((void**)&bqkv, g_bqkv);
    cudaGetSymbolAddress((void**)&Qb, g_Qb);
    cudaGetSymbolAddress((void**)&Kb, g_Kb);
    cudaGetSymbolAddress((void**)&Vb, g_Vb);
    cudaGetSymbolAddress((void**)&Cb, g_Cb);
    cudaGetSymbolAddress((void**)&Rp, g_R);

    cudaFuncSetAttribute(gemm_bf16<1>, cudaFuncAttributeMaxDynamicSharedMemorySize, GEMM_SMEM);
    cudaFuncSetAttribute(gemm_bf16<0>, cudaFuncAttributeMaxDynamicSharedMemorySize, GEMM_SMEM);
    cudaFuncSetAttribute(attn_bf16, cudaFuncAttributeMaxDynamicSharedMemorySize, ATT_SMEM);

    // single fused convert + bias pack
    cvt_all<<<2048, 256>>>(x, wq, wk, wv, wo, bq, bk, bv, xb, wqkv, wob, bqkv);

    // fused QKV projection: [4096,1024] x [3072,1024]^T (Q pre-scaled by EXP_C)
    dim3 gq(3*DD/128, MM/128);   // (24, 32)
    gemm_bf16<1><<<gq, 256, GEMM_SMEM>>>(xb, wqkv, bqkv, Qb, Kb, Vb, nullptr, MM, 3*DD, DD);

    attn_bf16<<<dim3(SS/128, HH, BB), 256, ATT_SMEM>>>(Qb, Kb, Vb, Cb);

    dim3 go(DD/128, MM/128);     // (8, 32)
    gemm_bf16<0><<<go, 256, GEMM_SMEM>>>(Cb, wob, bo, nullptr, nullptr, nullptr, Rp, MM, DD, DD);

    add_ln_kernel<<<MM, 256>>>(x, Rp, gamma, beta, out);
}

// round 17
// speedup vs baseline: 1.5190x; 1.5190x over previous
#include <cuda_runtime.h>
#include <cuda_bf16.h>
#include <math.h>
#include <stdint.h>

// Problem constants
#define BB 2
#define SS 2048
#define DD 1024
#define HH 16
#define HDD 64
#define MM (BB*SS)            // 4096
#define LN_EPS 1e-5f
#define EXP_C 0.04508422f     // (1/32) * log2(e)

typedef __nv_bfloat16 bf16;
typedef __nv_bfloat162 bf162;

// Scratch (device globals: allocation-free)
__device__ bf16 g_xb[MM*DD];
__device__ bf16 g_wqkv[3*DD*DD];    // rows 0-1023: wq, 1024-2047: wk, 2048-3071: wv
__device__ bf16 g_wob[DD*DD];
__device__ float g_bqkv[3*DD];
__device__ bf16 g_Qb[MM*DD], g_Kb[MM*DD], g_Vb[MM*DD];
__device__ bf16 g_Cb[MM*DD];
__device__ float g_R[MM*DD];

// ---------------------------------------------------------------------------
// mma m16n8k16 bf16 (f32 accum) + ldmatrix helpers
// ---------------------------------------------------------------------------
#define MMA_BF16(d, a, b)                                                     \
    asm volatile(                                                             \
        "mma.sync.aligned.m16n8k16.row.col.f32.bf16.bf16.f32 "                \
        "{%0,%1,%2,%3}, {%4,%5,%6,%7}, {%8,%9}, {%0,%1,%2,%3};"               \
        : "+f"((d)[0]), "+f"((d)[1]), "+f"((d)[2]), "+f"((d)[3])              \
        : "r"((a)[0]), "r"((a)[1]), "r"((a)[2]), "r"((a)[3]),                 \
          "r"((b)[0]), "r"((b)[1]))

#define LDSM_X4(r0, r1, r2, r3, saddr)                                        \
    asm volatile(                                                             \
        "ldmatrix.sync.aligned.m8n8.x4.shared.b16 {%0,%1,%2,%3}, [%4];"       \
        : "=r"(r0), "=r"(r1), "=r"(r2), "=r"(r3) : "r"(saddr))

#define LDSM_X4T(r0, r1, r2, r3, saddr)                                       \
    asm volatile(                                                             \
        "ldmatrix.sync.aligned.m8n8.x4.trans.shared.b16 {%0,%1,%2,%3}, [%4];" \
        : "=r"(r0), "=r"(r1), "=r"(r2), "=r"(r3) : "r"(saddr))

__device__ __forceinline__ void cp16(uint32_t saddr, const void* gptr) {
    asm volatile("cp.async.cg.shared.global [%0], [%1], 16;" :: "r"(saddr), "l"(gptr));
}
__device__ __forceinline__ float ex2(float x) {
    float y;
    asm("ex2.approx.f32 %0, %1;" : "=f"(y) : "f"(x));
    return y;
}
__device__ __forceinline__ uint32_t pack_bf162(float a, float b) {
    uint32_t r;
    asm("cvt.rn.bf16x2.f32 %0, %1, %2;" : "=r"(r) : "f"(b), "f"(a));
    return r;
}
__device__ __forceinline__ uint32_t ld_u32(const bf16* p) {
    return *(const uint32_t*)p;
}

// ---------------------------------------------------------------------------
// Fused fp32 -> bf16 convert for x + 4 weights + bias pack (single launch)
// ---------------------------------------------------------------------------
__global__ __launch_bounds__(256) void cvt_all(
    const float* __restrict__ x,  const float* __restrict__ wq,
    const float* __restrict__ wk, const float* __restrict__ wv,
    const float* __restrict__ wo,
    const float* __restrict__ bq, const float* __restrict__ bk,
    const float* __restrict__ bv,
    bf16* __restrict__ xb, bf16* __restrict__ wqkv, bf16* __restrict__ wob,
    float* __restrict__ bqkv)
{
    const int NX = MM*DD/4;      // float4 count for x
    const int NW = DD*DD/4;      // float4 count per weight
    const int NB = DD/4;         // float4 count per bias
    const int total  = NX + 4*NW;
    const int total2 = total + 3*NB;
    int stride = gridDim.x * blockDim.x;
    for (int i = blockIdx.x * blockDim.x + threadIdx.x; i < total2; i += stride) {
        if (i < total) {
            const float* s; bf16* d; int j;
            if (i < NX) { s = x; d = xb; j = i; }
            else {
                int k = i - NX;
                int w = k / NW;
                j = k - w * NW;
                s = (w == 0) ? wq : (w == 1) ? wk : (w == 2) ? wv : wo;
                d = (w == 3) ? wob : wqkv + (size_t)w * DD * DD;
            }
            float4 v = ((const float4*)s)[j];
            bf162* dp = (bf162*)d;
            dp[2*j]   = __floats2bfloat162_rn(v.x, v.y);
            dp[2*j+1] = __floats2bfloat162_rn(v.z, v.w);
        } else {
            int k = i - total;
            int w = k / NB;
            int j = k - w * NB;
            const float* s = (w == 0) ? bq : (w == 1) ? bk : bv;
            ((float4*)bqkv)[w*NB + j] = ((const float4*)s)[j];
        }
    }
}

// ---------------------------------------------------------------------------
// GEMM (NT) bf16: C[M,N] = A[M,K] * B[N,K]^T + bias[N]
// 128x128 tile, BK=32, 256 threads (8 warps 2x4, warp tile 64x32).
// PROVEN round-10 pipeline: double buffer, load-next BEFORE wait, two syncs.
// ---------------------------------------------------------------------------
#define GST 40
#define GBUF (256*GST)   // elems per stage (A + B arrays)
#define GEMM_SMEM (2*GBUF*2)   // 40960 B

template<int ROUTE>
__global__ __launch_bounds__(256, 2) void gemm_bf16(
    const bf16* __restrict__ A, const bf16* __restrict__ B,
    const float* __restrict__ bias,
    bf16* __restrict__ O0, bf16* __restrict__ O1, bf16* __restrict__ O2,
    float* __restrict__ Ofp,
    int M, int N, int K)
{
    extern __shared__ bf16 smem[];
    const uint32_t sm_u32 = (uint32_t)__cvta_generic_to_shared(smem);

    const int bm = blockIdx.y * 128;
    const int bn = blockIdx.x * 128;
    const int tid = threadIdx.x;
    const int warp = tid >> 5, lane = tid & 31;
    const int g = lane >> 2, t4 = lane & 3;
    const int wm = (warp & 1) * 64;
    const int wn = (warp >> 1) * 32;

    const int lrow = tid >> 1;
    const int lch  = tid & 1;

    float acc[4][4][4];
    #pragma unroll
    for (int i = 0; i < 4; i++)
        #pragma unroll
        for (int j = 0; j < 4; j++)
            #pragma unroll
            for (int r = 0; r < 4; r++) acc[i][j][r] = 0.f;

    const bf16* gA = A + (size_t)(bm + lrow) * K;
    const bf16* gB = B + (size_t)(bn + lrow) * K;

    auto load_tile = [&](int kt, int buf) {
        uint32_t sbase = sm_u32 + 2u * (buf * GBUF + lrow * GST);
        #pragma unroll
        for (int cc = 0; cc < 2; cc++) {
            int c = lch + 2*cc;   // 0..3 (8-elem chunks)
            cp16(sbase + 16u*c, gA + kt + c*8);
            cp16(sbase + 2u*(128*GST) + 16u*c, gB + kt + c*8);
        }
        asm volatile("cp.async.commit_group;" ::: "memory");
    };

    load_tile(0, 0);
    int buf = 0;

    for (int kt = 0; kt < K; kt += 32) {
        if (kt + 32 < K) {
            load_tile(kt + 32, buf ^ 1);
            asm volatile("cp.async.wait_group 1;" ::: "memory");
        } else {
            asm volatile("cp.async.wait_group 0;" ::: "memory");
        }
        __syncthreads();

        const bf16* sA = smem + buf*GBUF;
        const bf16* sB = sA + 128*GST;

        #pragma unroll
        for (int ks = 0; ks < 2; ks++) {
            const int c = ks*16 + 2*t4;
            uint32_t ah[4][4];
            #pragma unroll
            for (int mt = 0; mt < 4; mt++) {
                int r0 = (wm + mt*16 + g) * GST + c;
                ah[mt][0] = ld_u32(sA + r0);
                ah[mt][1] = ld_u32(sA + r0 + 8*GST);
                ah[mt][2] = ld_u32(sA + r0 + 8);
                ah[mt][3] = ld_u32(sA + r0 + 8*GST + 8);
            }
            #pragma unroll
            for (int nt = 0; nt < 4; nt++) {
                int n0 = (wn + nt*8 + g) * GST + c;
                uint32_t bh[2];
                bh[0] = ld_u32(sB + n0);
                bh[1] = ld_u32(sB + n0 + 8);
                #pragma unroll
                for (int mt = 0; mt < 4; mt++)
                    MMA_BF16(acc[mt][nt], ah[mt], bh);
            }
        }
        __syncthreads();
        buf ^= 1;
    }

    // epilogue
    bf16* Obf = O0;
    int coff = bn;
    float osc = 1.0f;
    if (ROUTE) {
        int sect = bn >> 10;            // 0,1,2 (128-col blocks never straddle)
        Obf = (sect == 0) ? O0 : (sect == 1 ? O1 : O2);
        coff = bn & 1023;
        if (sect == 0) osc = EXP_C;     // pre-scale Q for fixed-base softmax
    }
    #pragma unroll
    for (int mt = 0; mt < 4; mt++) {
        #pragma unroll
        for (int nt = 0; nt < 4; nt++) {
            int row0 = bm + wm + mt*16 + g;
            int colg = bn + wn + nt*8 + 2*t4;       // for bias
            int col0 = coff + wn + nt*8 + 2*t4;     // for store
            float b0 = bias[colg], b1 = bias[colg + 1];
            float v00 = acc[mt][nt][0] + b0, v01 = acc[mt][nt][1] + b1;
            float v10 = acc[mt][nt][2] + b0, v11 = acc[mt][nt][3] + b1;
            if (ROUTE) {
                v00 *= osc; v01 *= osc; v10 *= osc; v11 *= osc;
                *(uint32_t*)(Obf + (size_t)row0 * DD + col0)       = pack_bf162(v00, v01);
                *(uint32_t*)(Obf + (size_t)(row0 + 8) * DD + col0) = pack_bf162(v10, v11);
            } else {
                *(float2*)(Ofp + (size_t)row0 * N + col0)       = make_float2(v00, v01);
                *(float2*)(Ofp + (size_t)(row0 + 8) * N + col0) = make_float2(v10, v11);
            }
        }
    }
}

// ---------------------------------------------------------------------------
// Flash attention bf16 (v4, measured ~143us):
//  - fixed-base softmax (Q pre-scaled by EXP_C in the QKV GEMM epilogue)
//  - P in registers; Q frags hoisted; ONE __syncthreads per kv tile
//  - K AND V double-buffered via cp.async (one group per tile)
//  - K frags via ldmatrix.x4; V^T frags via ldmatrix.x4.trans
// smem (bf16 units): K0 [0,64*AST) K1 [64*AST,128*AST)
//                    V0 [128*AST,192*AST) V1 [192*AST,256*AST)
// Qs [0,128*AST) aliases K0/K1 (dead after fragment extraction).
// ---------------------------------------------------------------------------
#define AST 72
#define ATT_SMEM (256*AST*2)   // 36864 B

__global__ __launch_bounds__(256, 2) void attn_bf16(
    const bf16* __restrict__ Q, const bf16* __restrict__ K,
    const bf16* __restrict__ V, bf16* __restrict__ O)
{
    extern __shared__ bf16 sm[];
    bf16* Qs = sm;
    const uint32_t sm_u32 = (uint32_t)__cvta_generic_to_shared(sm);

    const int q0 = blockIdx.x * 128;
    const int h  = blockIdx.y;
    const int b  = blockIdx.z;
    const int tid = threadIdx.x;
    const int warp = tid >> 5, lane = tid & 31;
    const int g = lane >> 2, t4 = lane & 3;
    const int w16 = warp * 16;

    const int l8   = lane & 7;
    const int selK = (lane >> 3) & 1;
    const int selN = (lane >> 4) & 1;
    const uint32_t km_inv = (uint32_t)(((selN*8 + l8) * AST + selK*8) * 2);
    const uint32_t vm_inv = (uint32_t)(((selK*8 + l8) * AST + selN*8) * 2);

    const size_t base = (size_t)b * SS * DD + (size_t)h * HDD;

    // ---- load Q tile (128 x 64) into Qs (aliases K bufs) ----
    {
        int r = tid >> 1;
        int c0 = (tid & 1) * 32;
        const bf16* src = Q + base + (size_t)(q0 + r) * DD + c0;
        bf16* dst = Qs + r*AST + c0;
        #pragma unroll
        for (int i = 0; i < 4; i++)
            *(uint4*)(dst + i*8) = *(const uint4*)(src + i*8);
    }
    __syncthreads();   // Qs ready

    // ---- hoist Q fragments ----
    uint32_t qa[4][4];
    #pragma unroll
    for (int ks = 0; ks < 4; ks++) {
        const int c = ks*16 + 2*t4;
        int r0 = (w16 + g) * AST + c;
        qa[ks][0] = ld_u32(Qs + r0);
        qa[ks][1] = ld_u32(Qs + r0 + 8*AST);
        qa[ks][2] = ld_u32(Qs + r0 + 8);
        qa[ks][3] = ld_u32(Qs + r0 + 8*AST + 8);
    }
    __syncthreads();   // all warps extracted; Qs region reusable

    // ---- per-tile load (K and V identical pattern) ----
    const int kr  = tid >> 2;            // 0..63
    const int kc0 = (tid & 3) * 16;      // 0,16,32,48
    auto issue_tile = [&](int it, int bsel) {
        uint32_t kb = sm_u32 + 2u*(bsel*64*AST)       + 2u*(kr*AST + kc0);
        uint32_t vb = sm_u32 + 2u*((2 + bsel)*64*AST) + 2u*(kr*AST + kc0);
        const bf16* kg = K + base + (size_t)(it*64 + kr) * DD + kc0;
        const bf16* vg = V + base + (size_t)(it*64 + kr) * DD + kc0;
        cp16(kb,       kg);
        cp16(kb + 16u, kg + 8);
        cp16(vb,       vg);
        cp16(vb + 16u, vg + 8);
        asm volatile("cp.async.commit_group;" ::: "memory");
    };
    issue_tile(0, 0);

    float o[8][4];
    #pragma unroll
    for (int nf = 0; nf < 8; nf++)
        #pragma unroll
        for (int r = 0; r < 4; r++) o[nf][r] = 0.f;
    float lsum[2] = {0.f, 0.f};

    int buf = 0;
    for (int it = 0; it < SS/64; it++) {
        asm volatile("cp.async.wait_group 0;" ::: "memory");
        __syncthreads();   // tile it visible; all warps done with prev bufs
        if (it + 1 < SS/64) issue_tile(it + 1, buf ^ 1);

        const uint32_t kbase = sm_u32 + 2u*(buf*64*AST);
        const uint32_t vbase = sm_u32 + 2u*((2 + buf)*64*AST);

        // S = Q K^T
        float s[8][4];
        #pragma unroll
        for (int nf = 0; nf < 8; nf++)
            #pragma unroll
            for (int r = 0; r < 4; r++) s[nf][r] = 0.f;

        #pragma unroll
        for (int ks = 0; ks < 4; ks++) {
            #pragma unroll
            for (int i = 0; i < 4; i++) {
                uint32_t b0, b1, b2, b3;
                uint32_t addr = kbase + km_inv + (uint32_t)(i*16*AST*2 + ks*32);
                LDSM_X4(b0, b1, b2, b3, addr);
                uint32_t be[2]  = {b0, b1};
                uint32_t bo_[2] = {b2, b3};
                MMA_BF16(s[2*i],     qa[ks], be);
                MMA_BF16(s[2*i + 1], qa[ks], bo_);
            }
        }

        // p = exp2(s) (Q pre-scaled); accumulate row sums
        #pragma unroll
        for (int nf = 0; nf < 8; nf++) {
            s[nf][0] = ex2(s[nf][0]);
            s[nf][1] = ex2(s[nf][1]);
            s[nf][2] = ex2(s[nf][2]);
            s[nf][3] = ex2(s[nf][3]);
            lsum[0] += s[nf][0] + s[nf][1];
            lsum[1] += s[nf][2] + s[nf][3];
        }

        // O += P @ V   (V^T frags via ldmatrix.x4.trans on row-major V tile)
        #pragma unroll
        for (int ks = 0; ks < 4; ks++) {
            uint32_t pa[4];
            pa[0] = pack_bf162(s[2*ks][0],   s[2*ks][1]);
            pa[1] = pack_bf162(s[2*ks][2],   s[2*ks][3]);
            pa[2] = pack_bf162(s[2*ks+1][0], s[2*ks+1][1]);
            pa[3] = pack_bf162(s[2*ks+1][2], s[2*ks+1][3]);
            #pragma unroll
            for (int i = 0; i < 4; i++) {
                uint32_t b0, b1, b2, b3;
                uint32_t addr = vbase + vm_inv + (uint32_t)(ks*16*AST*2 + i*32);
                LDSM_X4T(b0, b1, b2, b3, addr);
                uint32_t be[2]  = {b0, b1};
                uint32_t bo_[2] = {b2, b3};
                MMA_BF16(o[2*i],     pa, be);
                MMA_BF16(o[2*i + 1], pa, bo_);
            }
        }
        buf ^= 1;
    }

    lsum[0] += __shfl_xor_sync(0xffffffffu, lsum[0], 1);
    lsum[0] += __shfl_xor_sync(0xffffffffu, lsum[0], 2);
    lsum[1] += __shfl_xor_sync(0xffffffffu, lsum[1], 1);
    lsum[1] += __shfl_xor_sync(0xffffffffu, lsum[1], 2);

    float inv0 = 1.f / lsum[0];
    float inv1 = 1.f / lsum[1];
    #pragma unroll
    for (int nf = 0; nf < 8; nf++) {
        int row0 = q0 + w16 + g;
        int col  = nf*8 + 2*t4;
        size_t o0 = base + (size_t)row0 * DD + col;
        size_t o1 = base + (size_t)(row0 + 8) * DD + col;
        *(uint32_t*)(O + o0) = pack_bf162(o[nf][0]*inv0, o[nf][1]*inv0);
        *(uint32_t*)(O + o1) = pack_bf162(o[nf][2]*inv1, o[nf][3]*inv1);
    }
}

// ---------------------------------------------------------------------------
// Fused residual-add + LayerNorm
// ---------------------------------------------------------------------------
__global__ __launch_bounds__(256) void add_ln_kernel(
    const float* __restrict__ x, const float* __restrict__ res,
    const float* __restrict__ gamma, const float* __restrict__ beta,
    float* __restrict__ out)
{
    const int row = blockIdx.x;
    const int t = threadIdx.x;
    const size_t off = (size_t)row * DD + t*4;

    float4 xv = *(const float4*)(x + off);
    float4 rv = *(const float4*)(res + off);
    float4 y;
    y.x = xv.x + rv.x; y.y = xv.y + rv.y; y.z = xv.z + rv.z; y.w = xv.w + rv.w;

    float sum = y.x + y.y + y.z + y.w;
    float sq  = y.x*y.x + y.y*y.y + y.z*y.z + y.w*y.w;

    #pragma unroll
    for (int msk = 16; msk >= 1; msk >>= 1) {
        sum += __shfl_xor_sync(0xffffffffu, sum, msk);
        sq  += __shfl_xor_sync(0xffffffffu, sq,  msk);
    }
    __shared__ float ssum[8], ssq[8], s_mu, s_rstd;
    int wid = t >> 5, lane = t & 31;
    if (lane == 0) { ssum[wid] = sum; ssq[wid] = sq; }
    __syncthreads();
    if (t == 0) {
        float ts = 0.f, tq = 0.f;
        #pragma unroll
        for (int i = 0; i < 8; i++) { ts += ssum[i]; tq += ssq[i]; }
        float mu = ts * (1.0f / DD);
        float var = tq * (1.0f / DD) - mu * mu;
        s_mu = mu;
        s_rstd = rsqrtf(var + LN_EPS);
    }
    __syncthreads();
    float mu = s_mu, rstd = s_rstd;

    float4 gv = *(const float4*)(gamma + t*4);
    float4 bv = *(const float4*)(beta + t*4);
    float4 oo;
    oo.x = (y.x - mu) * rstd * gv.x + bv.x;
    oo.y = (y.y - mu) * rstd * gv.y + bv.y;
    oo.z = (y.z - mu) * rstd * gv.z + bv.z;
    oo.w = (y.w - mu) * rstd * gv.w + bv.w;
    *(float4*)(out + off) = oo;
}

// ---------------------------------------------------------------------------
extern "C" void kernel_launch(void* const* d_in, const int* in_sizes, int n_in,
                              void* d_out, int out_size)
{
    const float* x     = (const float*)d_in[0];
    const float* wq    = (const float*)d_in[1];
    const float* bq    = (const float*)d_in[2];
    const float* wk    = (const float*)d_in[3];
    const float* bk    = (const float*)d_in[4];
    const float* wv    = (const float*)d_in[5];
    const float* bv    = (const float*)d_in[6];
    const float* wo    = (const float*)d_in[7];
    const float* bo    = (const float*)d_in[8];
    const float* gamma = (const float*)d_in[9];
    const float* beta  = (const float*)d_in[10];
    float* out = (float*)d_out;

    bf16 *xb, *wqkv, *wob, *Qb, *Kb, *Vb, *Cb;
    float *bqkv, *Rp;
    cudaGetSymbolAddress((void**)&xb, g_xb);
    cudaGetSymbolAddress((void**)&wqkv, g_wqkv);
    cudaGetSymbolAddress((void**)&wob, g_wob);
    cudaGetSymbolAddress((void**)&bqkv, g_bqkv);
    cudaGetSymbolAddress((void**)&Qb, g_Qb);
    cudaGetSymbolAddress((void**)&Kb, g_Kb);
    cudaGetSymbolAddress((void**)&Vb, g_Vb);
    cudaGetSymbolAddress((void**)&Cb, g_Cb);
    cudaGetSymbolAddress((void**)&Rp, g_R);

    cudaFuncSetAttribute(gemm_bf16<1>, cudaFuncAttributeMaxDynamicSharedMemorySize, GEMM_SMEM);
    cudaFuncSetAttribute(gemm_bf16<0>, cudaFuncAttributeMaxDynamicSharedMemorySize, GEMM_SMEM);
    cudaFuncSetAttribute(attn_bf16, cudaFuncAttributeMaxDynamicSharedMemorySize, ATT_SMEM);

    // single fused convert + bias pack
    cvt_all<<<2048, 256>>>(x, wq, wk, wv, wo, bq, bk, bv, xb, wqkv, wob, bqkv);

    // fused QKV projection: [4096,1024] x [3072,1024]^T (Q pre-scaled by EXP_C)
    dim3 gq(3*DD/128, MM/128);   // (24, 32)
    gemm_bf16<1><<<gq, 256, GEMM_SMEM>>>(xb, wqkv, bqkv, Qb, Kb, Vb, nullptr, MM, 3*DD, DD);

    attn_bf16<<<dim3(SS/128, HH, BB), 256, ATT_SMEM>>>(Qb, Kb, Vb, Cb);

    dim3 go(DD/128, MM/128);     // (8, 32)
    gemm_bf16<0><<<go, 256, GEMM_SMEM>>>(Cb, wob, bo, nullptr, nullptr, nullptr, Rp, MM, DD, DD);

    add_ln_kernel<<<MM, 256>>>(x, Rp, gamma, beta, out);
}